// round 6
// baseline (speedup 1.0000x reference)
#include <cuda_runtime.h>
#include <cstdint>

#define KTOT   4194304
#define CHUNK  32                       // outputs per chain
#define WARM   128                      // warmup (redundant) steps per chain
#define TS     16                       // steps per tile
#define NT     ((WARM + CHUNK) / TS)    // 10 tiles
#define WTILES (WARM / TS)              // 8 warmup tiles
#define NCH    (KTOT / CHUNK)           // 131072 chains
#define CPW    64                       // chains per warp (ILP=2 per thread)
#define NWARP  (NCH / CPW)              // 2048 warps
#define WPB    2                        // warps per block
#define TPB    (WPB * 32)
#define NBLK   (NWARP / WPB)            // 1024 blocks
#define PITCH  18                       // smem row pitch in floats (8B-aligned)

__device__ __forceinline__ float frcp_ap(float x) {
    float r; asm("rcp.approx.ftz.f32 %0, %1;" : "=f"(r) : "f"(x)); return r;
}
__device__ __forceinline__ float fsqrt_ap(float x) {
    float r; asm("sqrt.approx.f32 %0, %1;" : "=f"(r) : "f"(x)); return r;
}
__device__ __forceinline__ void cp_async8(uint32_t dst, const float* src) {
    asm volatile("cp.async.ca.shared.global [%0], [%1], 8;" :: "r"(dst), "l"(src));
}
#define CP_COMMIT() asm volatile("cp.async.commit_group;" ::: "memory")
#define CP_WAIT1()  asm volatile("cp.async.wait_group 1;"  ::: "memory")
#define CP_WAIT0()  asm volatile("cp.async.wait_group 0;"  ::: "memory")

struct P { float nu, Amu, As, bmu, Bs, wmu, ws; };

__device__ __forceinline__ void gas_step(const float y, float& mu, float& s2, const P& p) {
    // scale*r = (nu+1)*s2*r / (nu*s2 + r^2): one rcp, 10 fma-pipe ops
    const float r_  = y - mu;
    const float rr  = r_ * r_;
    const float d   = fmaf(p.nu, s2, rr);
    const float q   = frcp_ap(d);
    const float s2r = s2 * r_;
    const float mb  = fmaf(p.bmu, mu, p.wmu);   // off critical path
    const float sb  = fmaf(p.Bs,  s2, p.ws);    // off critical path
    const float N   = s2r * q;
    mu = fmaf(p.Amu, N, mb);
    s2 = fmaf(p.As, N * r_, sb);
}

// Stage tile tau (64 chains x 16 steps, 4KB) with 8B cp.async.
// lane covers rows r0+4k (r0=lane>>3), segment col=(lane&7)*2 -> 64B coalesced
// chunks per 8 lanes. 16 transfers per lane, incremental addressing.
template<bool GUARD>
__device__ __forceinline__ void stage_tile(
    const int tau, const int wcb, const int lane,
    const float* __restrict__ y, float (*buf)[PITCH])
{
    const int r0  = lane >> 3;
    const int col = (lane & 7) * 2;
    uint32_t dst = (uint32_t)__cvta_generic_to_shared(&buf[r0][col]);
    const int gbase = (wcb + r0) * CHUNK - WARM + tau * TS + col;
    #pragma unroll
    for (int k = 0; k < 16; ++k) {
        int g = gbase + k * (4 * CHUNK);           // 4 rows per k
        if (GUARD) g = max(g, 0);                  // pre-t0 slots: skipped anyway
        cp_async8(dst + k * (4 * PITCH * 4), y + g);
    }
    CP_COMMIT();
}

// Run TS steps for BOTH chains (A = row lane, B = row lane+32).
template<bool GUARD, bool EMIT>
__device__ __forceinline__ void compute_tile(
    const int tau, const int lane, const int skipA,
    float (*bufc)[PITCH], float (*sg)[PITCH],
    float& muA, float& s2A, float& muB, float& s2B, const P& p)
{
    #pragma unroll
    for (int s = 0; s < TS; s += 2) {
        const float2 ya = *reinterpret_cast<const float2*>(&bufc[lane][s]);
        const float2 yb = *reinterpret_cast<const float2*>(&bufc[lane + 32][s]);
        if (GUARD) {
            if (tau * TS + s     >= skipA) gas_step(ya.x, muA, s2A, p);
            gas_step(yb.x, muB, s2B, p);
            if (tau * TS + s + 1 >= skipA) gas_step(ya.y, muA, s2A, p);
            gas_step(yb.y, muB, s2B, p);
        } else {
            gas_step(ya.x, muA, s2A, p);
            gas_step(yb.x, muB, s2B, p);
            const float mA0 = muA, vA0 = s2A, mB0 = muB, vB0 = s2B;
            gas_step(ya.y, muA, s2A, p);
            gas_step(yb.y, muB, s2B, p);
            if (EMIT) {
                float2 m, g;
                m.x = mA0; m.y = muA;
                g.x = fsqrt_ap(vA0); g.y = fsqrt_ap(s2A);
                *reinterpret_cast<float2*>(&bufc[lane][s]) = m;      // mu in place
                *reinterpret_cast<float2*>(&sg[lane][s])   = g;
                m.x = mB0; m.y = muB;
                g.x = fsqrt_ap(vB0); g.y = fsqrt_ap(s2B);
                *reinterpret_cast<float2*>(&bufc[lane + 32][s]) = m;
                *reinterpret_cast<float2*>(&sg[lane + 32][s])   = g;
            }
        }
    }
}

// Coalesced flush of an emit tile (same lane->row/col map as staging).
__device__ __forceinline__ void flush_tile(
    const int tau, const int wcb, const int lane,
    const float (*bufc)[PITCH], const float (*sg)[PITCH], float* __restrict__ out)
{
    const int r0  = lane >> 3;
    const int col = (lane & 7) * 2;
    const int ob  = (tau - WTILES) * TS;
    #pragma unroll
    for (int k = 0; k < 16; ++k) {
        const int row = r0 + 4 * k;
        const float2 m = *reinterpret_cast<const float2*>(&bufc[row][col]);
        const float2 g = *reinterpret_cast<const float2*>(&sg[row][col]);
        const int gi = (wcb + row) * CHUNK + ob + col;
        *reinterpret_cast<float2*>(&out[gi])        = m;
        *reinterpret_cast<float2*>(&out[KTOT + gi]) = g;
    }
}

template<bool GUARD>
__device__ __forceinline__ void run_warp(
    const int wcb, const int lane,
    const float* __restrict__ y, float* __restrict__ out,
    float (*buf)[CPW][PITCH], float (*sg)[PITCH],
    float muA, float s2A, float muB, float s2B, const P& p, const int skipA)
{
    stage_tile<GUARD>(0, wcb, lane, y, buf[0]);
    stage_tile<GUARD>(1, wcb, lane, y, buf[1]);
    #pragma unroll 1
    for (int t = 0; t < NT; ++t) {
        if (t < NT - 1) CP_WAIT1(); else CP_WAIT0();
        __syncwarp();
        float (*bufc)[PITCH] = buf[t & 1];
        if (t < WTILES)
            compute_tile<GUARD, false>(t, lane, skipA, bufc, sg, muA, s2A, muB, s2B, p);
        else
            compute_tile<false, true>(t, lane, skipA, bufc, sg, muA, s2A, muB, s2B, p);
        __syncwarp();
        if (t + 2 < NT)       stage_tile<GUARD>(t + 2, wcb, lane, y, buf[t & 1]);
        else if (t >= WTILES) flush_tile(t, wcb, lane, bufc, sg, out);
    }
}

__global__ __launch_bounds__(TPB, 8)
void argas_kernel(
    const float* __restrict__ y,
    const float* __restrict__ p_lastmu,  const float* __restrict__ p_lastsig,
    const float* __restrict__ p_amu,     const float* __restrict__ p_as,
    const float* __restrict__ p_bmu,     const float* __restrict__ p_bs,
    const float* __restrict__ p_wmu,     const float* __restrict__ p_ws,
    const float* __restrict__ p_nu,      const float* __restrict__ p_str,
    float* __restrict__ out)
{
    __shared__ float buf[WPB][2][CPW][PITCH];   // per-warp double-buffered tiles
    __shared__ float sg[WPB][CPW][PITCH];       // per-warp sigma staging

    const int warp = threadIdx.x >> 5;
    const int lane = threadIdx.x & 31;
    const int wcb  = (blockIdx.x * WPB + warp) * CPW;   // warp's chain base

    P p;
    const float nu       = *p_nu;
    const float strength = *p_str;
    const float amu  = (*p_amu) * strength;
    const float as_  = (*p_as)  * strength;
    const float bmu  = *p_bmu;
    const float bs   = *p_bs;
    const float nup1 = nu + 1.0f;
    p.nu  = nu;
    p.Amu = bmu * amu * nup1;
    p.As  = bs  * as_ * nup1;
    p.bmu = bmu;
    p.Bs  = bs * (1.0f - as_);
    p.wmu = *p_wmu;
    p.ws  = *p_ws;

    const float mu0 = *p_lastmu;   // chains whose warmup reaches before idx 0
    const float s20 = *p_lastsig;  // skip those steps; they start exact.

    // chain A = wcb+lane, chain B = wcb+32+lane. Only chains 0..3 (warp 0,
    // lanes 0..3, A side) have warmup windows reaching before index 0.
    const int skipA = WARM - (wcb + lane) * CHUNK;   // >0 only for those

    if (wcb == 0)
        run_warp<true >(wcb, lane, y, out, buf[warp], sg[warp],
                        mu0, s20, mu0, s20, p, skipA);
    else
        run_warp<false>(wcb, lane, y, out, buf[warp], sg[warp],
                        mu0, s20, mu0, s20, p, skipA);
}

extern "C" void kernel_launch(void* const* d_in, const int* in_sizes, int n_in,
                              void* d_out, int out_size) {
    const float* y = (const float*)d_in[0];
    argas_kernel<<<NBLK, TPB>>>(
        y,
        (const float*)d_in[1],  (const float*)d_in[2],
        (const float*)d_in[3],  (const float*)d_in[4],
        (const float*)d_in[5],  (const float*)d_in[6],
        (const float*)d_in[7],  (const float*)d_in[8],
        (const float*)d_in[9],  (const float*)d_in[10],
        (float*)d_out);
}